// round 13
// baseline (speedup 1.0000x reference)
#include <cuda_runtime.h>
#include <cuda_fp16.h>
#include <stdint.h>

#define N_TOK 16384
#define D_DIM 2048
#define H_DIM 1024
#define N_EXP 16

// ------------------------- scratch (device globals; no allocs) -------------
__device__ __half g_xh[(size_t)N_TOK * D_DIM];
__device__ __half g_w1h[(size_t)N_EXP * 2 * H_DIM * D_DIM];  // row-interleaved up/gate
__device__ __half g_w2th[(size_t)N_EXP * D_DIM * H_DIM];     // transposed w_down
__device__ __half g_hh[(size_t)N_TOK * H_DIM];

// ------------------------- PTX helpers (compute_103-legal only) ------------
__device__ __forceinline__ uint32_t smem_u32(const void* p) {
    uint32_t a;
    asm("{ .reg .u64 t; cvta.to.shared.u64 t, %1; cvt.u32.u64 %0, t; }"
        : "=r"(a) : "l"(p));
    return a;
}

__device__ __forceinline__ void cp16(uint32_t dst, const void* src) {
    asm volatile("cp.async.cg.shared.global [%0], [%1], 16;\n"
                 :: "r"(dst), "l"(src));
}
__device__ __forceinline__ void cp_commit() {
    asm volatile("cp.async.commit_group;\n" ::: "memory");
}
template <int NN>
__device__ __forceinline__ void cp_wait() {
    asm volatile("cp.async.wait_group %0;\n" :: "n"(NN) : "memory");
}

__device__ __forceinline__ void ldsm4(uint32_t* r, uint32_t addr) {
    asm volatile("ldmatrix.sync.aligned.m8n8.x4.shared.b16 {%0,%1,%2,%3}, [%4];"
                 : "=r"(r[0]), "=r"(r[1]), "=r"(r[2]), "=r"(r[3]) : "r"(addr));
}

__device__ __forceinline__ void mma16816(float* c, const uint32_t* a,
                                         uint32_t b0, uint32_t b1) {
    asm volatile(
        "mma.sync.aligned.m16n8k16.row.col.f32.f16.f16.f32 "
        "{%0,%1,%2,%3}, {%4,%5,%6,%7}, {%8,%9}, {%0,%1,%2,%3};"
        : "+f"(c[0]), "+f"(c[1]), "+f"(c[2]), "+f"(c[3])
        : "r"(a[0]), "r"(a[1]), "r"(a[2]), "r"(a[3]), "r"(b0), "r"(b1));
}

// ------------------------- pre-pass kernels --------------------------------
__global__ void __launch_bounds__(256) cvt_kernel(
    const float* __restrict__ src, __half* __restrict__ dst) {
    size_t i = (size_t)blockIdx.x * blockDim.x + threadIdx.x;
    float4 v = reinterpret_cast<const float4*>(src)[i];
    __half hv[4];
    float f[4] = {v.x, v.y, v.z, v.w};
#pragma unroll
    for (int k = 0; k < 4; k++) hv[k] = __float2half(f[k]);
    reinterpret_cast<uint2*>(dst)[i] = *reinterpret_cast<uint2*>(hv);
}

// w1 [E,2048,D] (up rows 0-1023, gate 1024-2047) -> row-interleaved fp16
__global__ void __launch_bounds__(256) interleave_cvt_kernel(
    const float* __restrict__ w, __half* __restrict__ dst) {
    size_t i = (size_t)blockIdx.x * blockDim.x + threadIdx.x;  // float4 idx
    size_t row = i >> 9;
    size_t c4 = (i & 511) << 2;
    int e = (int)(row >> 11);
    int r = (int)(row & 2047);
    int nr = (r < 1024) ? (2 * r) : (2 * (r - 1024) + 1);
    float4 v = *reinterpret_cast<const float4*>(w + row * D_DIM + c4);
    __half hv[4];
    float f[4] = {v.x, v.y, v.z, v.w};
#pragma unroll
    for (int k = 0; k < 4; k++) hv[k] = __float2half(f[k]);
    size_t o4 = (((size_t)e * 2048 + nr) * D_DIM + c4) >> 2;
    reinterpret_cast<uint2*>(dst)[o4] = *reinterpret_cast<uint2*>(hv);
}

// w_down [E,H,D] -> w2t [E,D,H] fp16
__global__ void __launch_bounds__(256) transpose_cvt_kernel(
    const float* __restrict__ w, __half* __restrict__ th) {
    __shared__ float tile[32][33];
    int e = blockIdx.z, hb = blockIdx.y, db = blockIdx.x;
    int tx = threadIdx.x, ty = threadIdx.y;  // 32 x 8
    const float* src = w + ((size_t)e * H_DIM + hb * 32) * D_DIM + db * 32;
#pragma unroll
    for (int j = 0; j < 32; j += 8)
        tile[ty + j][tx] = src[(size_t)(ty + j) * D_DIM + tx];
    __syncthreads();
    size_t ob = ((size_t)e * D_DIM + db * 32) * H_DIM + hb * 32;
#pragma unroll
    for (int j = 0; j < 32; j += 8)
        th[ob + (size_t)(ty + j) * H_DIM + tx] = __float2half(tile[tx][ty + j]);
}

// ------------------------- GEMM (fp16, mma.sync) ---------------------------
// C = A x B^T.  CTA tile 128(m) x 128(n), 256 threads (8 warps, 4m x 2n,
// warp tile 32x64). kchunk 64 (128B rows, SW128). 3-stage ring, 1
// barrier/chunk, 2 CTAs/SM. Per-warp k16 PHASE stagger: odd warps process
// k-slices in rotated order so LDSM bursts from half the warps overlap MMA
// bursts from the other half (smem port <-> tensor pipe de-synchronization).
#define OFF_B  16384
#define STAGE_BYTES 32768            // A(16K) + B(16K)
#define GEMM_SMEM (3 * STAGE_BYTES)  // 96KB -> 2 CTAs/SM

template <int K, bool FUSE_SILU>
__global__ void __launch_bounds__(256, 2) gemmf_kernel(
    const __half* __restrict__ A, const __half* __restrict__ B,
    float* __restrict__ C, __half* __restrict__ H) {
    extern __shared__ char smem[];
    uint32_t sbase = smem_u32(smem);
    int tid = threadIdx.x, wid = tid >> 5, lane = tid & 31;
    int bx = blockIdx.x;
    int e = bx >> 7, rr = bx & 127, mt = rr >> 4, nt = rr & 15;

    // per-thread loader global pointers (bytes); constant strides thereafter
    int lrow = tid >> 3, lc16 = tid & 7;  // lrow 0..31, lc16 0..7
    const char* gA = (const char*)(A + ((size_t)e * 1024 + mt * 128 + lrow) * K +
                                   lc16 * 8);
    const char* gB = (const char*)(B + ((size_t)e * 2048 + nt * 128 + lrow) * K +
                                   lc16 * 8);
    // per-thread loader smem offset (swizzled once; +j*4096 carry-free since
    // soL < 4096)
    uint32_t soL = (uint32_t)(lrow * 128 + lc16 * 16);
    soL ^= (soL >> 3) & 0x70;

    float acc[2][8][4];
#pragma unroll
    for (int a = 0; a < 2; a++)
#pragma unroll
        for (int b = 0; b < 8; b++)
#pragma unroll
            for (int c = 0; c < 4; c++) acc[a][b][c] = 0.0f;

    int wm = wid & 3, wn = wid >> 2;  // 4m x 2n
    // per-warp k16 phase (bytes): odd warps start 2 k-slices in
    uint32_t phase = (uint32_t)((wid & 1) * 64);  // {0, 64} bytes = {0,2} k16

    // kchunk stride in bytes along K: 64 halves = 128 bytes
#define LOAD_STAGE(SB, KC)                                                    \
    do {                                                                      \
        const char* a0 = gA + (size_t)(KC)*128;                               \
        const char* b0 = gB + (size_t)(KC)*128;                               \
        _Pragma("unroll") for (int j = 0; j < 4; j++)                         \
            cp16((SB) + soL + j * 4096, a0 + (size_t)j * 32 * (K * 2));       \
        _Pragma("unroll") for (int j = 0; j < 4; j++)                         \
            cp16((SB) + OFF_B + soL + j * 4096, b0 + (size_t)j * 32 * (K * 2));\
    } while (0)

    uint32_t sb[3] = {sbase, sbase + STAGE_BYTES, sbase + 2 * STAGE_BYTES};
    constexpr int kiters = K >> 6;
    LOAD_STAGE(sb[0], 0);
    cp_commit();
    LOAD_STAGE(sb[1], 1);
    cp_commit();

    // ---- precomputed swizzled ldsm offsets (stage-local) ----
    // bases have bits 5-6 clear pre-swizzle, so for kd = k16*32 (bits 5-6):
    //   sw(base + kd) = sw(base) ^ kd   (XOR; add could carry through
    //                                    swizzled bits 4-6)
    uint32_t aOff[2], bOff[4];
    {
        uint32_t aBase =
            (uint32_t)((wm * 32 + (lane & 15)) * 128 + ((lane >> 4) & 1) * 16);
        uint32_t bBase =
            (uint32_t)((wn * 64 + (lane & 7) + ((lane >> 4) & 1) * 8) * 128 +
                       ((lane >> 3) & 1) * 16);
#pragma unroll
        for (int mf = 0; mf < 2; mf++) {
            uint32_t o = aBase + mf * 2048;
            aOff[mf] = o ^ ((o >> 3) & 0x70);
        }
#pragma unroll
        for (int np = 0; np < 4; np++) {
            uint32_t o = bBase + np * 2048;
            bOff[np] = (o ^ ((o >> 3) & 0x70)) + OFF_B;  // OFF_B bit14: safe
        }
    }

#pragma unroll 1
    for (int kc = 0; kc < kiters; kc++) {
        uint32_t s = sb[kc % 3];
        cp_wait<1>();
        __syncthreads();  // ring: stage loaded below was consumed last iter

        uint32_t af[2][2][4], bf[2][4][4];
        // prologue: fragments for this warp's FIRST k-slice (= phase)
#pragma unroll
        for (int mf = 0; mf < 2; mf++)
            ldsm4(af[0][mf], s + (aOff[mf] ^ phase));
#pragma unroll
        for (int np = 0; np < 4; np++)
            ldsm4(bf[0][np], s + (bOff[np] ^ phase));

#pragma unroll
        for (int j = 0; j < 4; j++) {
            int cur = j & 1, nxt = cur ^ 1;
            if (j < 3) {
                // next slice for this warp: (j+1)*32 rotated by phase, mod 128
                uint32_t kd = (((uint32_t)(j + 1) * 32 + phase) & 127);
#pragma unroll
                for (int mf = 0; mf < 2; mf++)
                    ldsm4(af[nxt][mf], s + (aOff[mf] ^ kd));
#pragma unroll
                for (int np = 0; np < 4; np++)
                    ldsm4(bf[nxt][np], s + (bOff[np] ^ kd));
            }
#pragma unroll
            for (int mf = 0; mf < 2; mf++)
#pragma unroll
                for (int np = 0; np < 4; np++) {
                    mma16816(acc[mf][2 * np], af[cur][mf], bf[cur][np][0],
                             bf[cur][np][1]);
                    mma16816(acc[mf][2 * np + 1], af[cur][mf], bf[cur][np][2],
                             bf[cur][np][3]);
                }
        }
        if (kc + 2 < kiters) LOAD_STAGE(sb[(kc + 2) % 3], kc + 2);
        cp_commit();
    }

    // ---- epilogue ----
    int row0 = wm * 32 + (lane >> 2);
    if (FUSE_SILU) {
        // interleaved cols: even = up, odd = gate. h = up * gate * sigmoid(gate)
        size_t grow0 = (size_t)e * 1024 + mt * 128 + row0;
        int hcol = nt * 64 + wn * 32 + (lane & 3);
#pragma unroll
        for (int mf = 0; mf < 2; mf++)
#pragma unroll
            for (int nf = 0; nf < 8; nf++) {
                size_t r = grow0 + mf * 16;
                int hc = hcol + nf * 4;
                float u0 = acc[mf][nf][0], g0 = acc[mf][nf][1];
                float u1 = acc[mf][nf][2], g1 = acc[mf][nf][3];
                float h0 = u0 * g0 * (1.0f / (1.0f + __expf(-g0)));
                float h1 = u1 * g1 * (1.0f / (1.0f + __expf(-g1)));
                H[r * H_DIM + hc] = __float2half(h0);
                H[(r + 8) * H_DIM + hc] = __float2half(h1);
            }
    } else {
        float* pC = C + ((size_t)e * 1024 + mt * 128) * 2048 + nt * 128;
        int col0 = wn * 64 + (lane & 3) * 2;
#pragma unroll
        for (int mf = 0; mf < 2; mf++)
#pragma unroll
            for (int nf = 0; nf < 8; nf++) {
                int r = row0 + mf * 16, c = col0 + nf * 8;
                float2 v0 = {acc[mf][nf][0], acc[mf][nf][1]};
                float2 v1 = {acc[mf][nf][2], acc[mf][nf][3]};
                *reinterpret_cast<float2*>(pC + (size_t)r * 2048 + c) = v0;
                *reinterpret_cast<float2*>(pC + (size_t)(r + 8) * 2048 + c) = v1;
            }
    }
#undef LOAD_STAGE
}

// ------------------------- launch ------------------------------------------
extern "C" void kernel_launch(void* const* d_in, const int* in_sizes, int n_in,
                              void* d_out, int out_size) {
    (void)in_sizes; (void)n_in; (void)out_size;
    const float* x = (const float*)d_in[0];
    const float* w1 = (const float*)d_in[1];
    const float* w2 = (const float*)d_in[2];
    float* out = (float*)d_out;

    cudaFuncSetAttribute(gemmf_kernel<D_DIM, true>,
                         cudaFuncAttributeMaxDynamicSharedMemorySize, GEMM_SMEM);
    cudaFuncSetAttribute(gemmf_kernel<H_DIM, false>,
                         cudaFuncAttributeMaxDynamicSharedMemorySize, GEMM_SMEM);

    __half *xh, *w1h, *w2th, *hh;
    cudaGetSymbolAddress((void**)&xh, g_xh);
    cudaGetSymbolAddress((void**)&w1h, g_w1h);
    cudaGetSymbolAddress((void**)&w2th, g_w2th);
    cudaGetSymbolAddress((void**)&hh, g_hh);

    // pre-pass: x -> fp16; w1 -> interleaved fp16; w2 -> transposed fp16
    cvt_kernel<<<32768, 256>>>(x, xh);
    interleave_cvt_kernel<<<65536, 256>>>(w1, w1h);
    transpose_cvt_kernel<<<dim3(64, 32, 16), dim3(32, 8)>>>(w2, w2th);

    // GEMM1: up/gate + fused silu -> h (fp16). grid: E * 8mt * 16nt
    gemmf_kernel<D_DIM, true><<<N_EXP * 128, 256, GEMM_SMEM>>>(
        xh, w1h, nullptr, hh);
    // GEMM2: out = h @ w2t^T. grid: E * 8mt * 16nt
    gemmf_kernel<H_DIM, false><<<N_EXP * 128, 256, GEMM_SMEM>>>(
        hh, w2th, out, nullptr);
}

// round 14
// speedup vs baseline: 1.0268x; 1.0268x over previous
#include <cuda_runtime.h>
#include <cuda_fp16.h>
#include <stdint.h>

#define N_TOK 16384
#define D_DIM 2048
#define H_DIM 1024
#define N_EXP 16

// ------------------------- scratch (device globals; no allocs) -------------
__device__ __half g_xh[(size_t)N_TOK * D_DIM];
__device__ __half g_w1h[(size_t)N_EXP * 2 * H_DIM * D_DIM];  // row-interleaved up/gate
__device__ __half g_w2th[(size_t)N_EXP * D_DIM * H_DIM];     // transposed w_down
__device__ __half g_hh[(size_t)N_TOK * H_DIM];
__device__ unsigned g_cnt[N_EXP * 8];  // per-(e,mt) gemm1 tile counters

// ------------------------- PTX helpers (compute_103-legal only) ------------
__device__ __forceinline__ uint32_t smem_u32(const void* p) {
    uint32_t a;
    asm("{ .reg .u64 t; cvta.to.shared.u64 t, %1; cvt.u32.u64 %0, t; }"
        : "=r"(a) : "l"(p));
    return a;
}

__device__ __forceinline__ void cp16(uint32_t dst, const void* src) {
    asm volatile("cp.async.cg.shared.global [%0], [%1], 16;\n"
                 :: "r"(dst), "l"(src));
}
__device__ __forceinline__ void cp_commit() {
    asm volatile("cp.async.commit_group;\n" ::: "memory");
}
template <int NN>
__device__ __forceinline__ void cp_wait() {
    asm volatile("cp.async.wait_group %0;\n" :: "n"(NN) : "memory");
}

__device__ __forceinline__ void ldsm4(uint32_t* r, uint32_t addr) {
    asm volatile("ldmatrix.sync.aligned.m8n8.x4.shared.b16 {%0,%1,%2,%3}, [%4];"
                 : "=r"(r[0]), "=r"(r[1]), "=r"(r[2]), "=r"(r[3]) : "r"(addr));
}

__device__ __forceinline__ void mma16816(float* c, const uint32_t* a,
                                         uint32_t b0, uint32_t b1) {
    asm volatile(
        "mma.sync.aligned.m16n8k16.row.col.f32.f16.f16.f32 "
        "{%0,%1,%2,%3}, {%4,%5,%6,%7}, {%8,%9}, {%0,%1,%2,%3};"
        : "+f"(c[0]), "+f"(c[1]), "+f"(c[2]), "+f"(c[3])
        : "r"(a[0]), "r"(a[1]), "r"(a[2]), "r"(a[3]), "r"(b0), "r"(b1));
}

// ------------------------- pre-pass kernels --------------------------------
__global__ void __launch_bounds__(256) cvt_kernel(
    const float* __restrict__ src, __half* __restrict__ dst) {
    size_t i = (size_t)blockIdx.x * blockDim.x + threadIdx.x;
    float4 v = reinterpret_cast<const float4*>(src)[i];
    __half hv[4];
    float f[4] = {v.x, v.y, v.z, v.w};
#pragma unroll
    for (int k = 0; k < 4; k++) hv[k] = __float2half(f[k]);
    reinterpret_cast<uint2*>(dst)[i] = *reinterpret_cast<uint2*>(hv);
}

// w1 [E,2048,D] (up rows 0-1023, gate 1024-2047) -> row-interleaved fp16
__global__ void __launch_bounds__(256) interleave_cvt_kernel(
    const float* __restrict__ w, __half* __restrict__ dst) {
    size_t i = (size_t)blockIdx.x * blockDim.x + threadIdx.x;  // float4 idx
    size_t row = i >> 9;
    size_t c4 = (i & 511) << 2;
    int e = (int)(row >> 11);
    int r = (int)(row & 2047);
    int nr = (r < 1024) ? (2 * r) : (2 * (r - 1024) + 1);
    float4 v = *reinterpret_cast<const float4*>(w + row * D_DIM + c4);
    __half hv[4];
    float f[4] = {v.x, v.y, v.z, v.w};
#pragma unroll
    for (int k = 0; k < 4; k++) hv[k] = __float2half(f[k]);
    size_t o4 = (((size_t)e * 2048 + nr) * D_DIM + c4) >> 2;
    reinterpret_cast<uint2*>(dst)[o4] = *reinterpret_cast<uint2*>(hv);
}

// w_down [E,H,D] -> w2t [E,D,H] fp16
__global__ void __launch_bounds__(256) transpose_cvt_kernel(
    const float* __restrict__ w, __half* __restrict__ th) {
    __shared__ float tile[32][33];
    int e = blockIdx.z, hb = blockIdx.y, db = blockIdx.x;
    int tx = threadIdx.x, ty = threadIdx.y;  // 32 x 8
    const float* src = w + ((size_t)e * H_DIM + hb * 32) * D_DIM + db * 32;
#pragma unroll
    for (int j = 0; j < 32; j += 8)
        tile[ty + j][tx] = src[(size_t)(ty + j) * D_DIM + tx];
    __syncthreads();
    size_t ob = ((size_t)e * D_DIM + db * 32) * H_DIM + hb * 32;
#pragma unroll
    for (int j = 0; j < 32; j += 8)
        th[ob + (size_t)(ty + j) * H_DIM + tx] = __float2half(tile[tx][ty + j]);
}

// ------------------------- GEMM body (round-10 structure) ------------------
// C = A x B^T.  CTA tile 128(m) x 128(n), 256 threads (8 warps, 4m x 2n,
// warp tile 32x64). kchunk 64 (128B rows, SW128). 3-stage ring, 1
// barrier/chunk, 2 CTAs/SM.
#define OFF_B  16384
#define STAGE_BYTES 32768            // A(16K) + B(16K)
#define GEMM_SMEM (3 * STAGE_BYTES)  // 96KB -> 2 CTAs/SM

template <int K, bool FUSE_SILU>
__device__ __forceinline__ void gemm_body(
    const __half* __restrict__ A, const __half* __restrict__ B,
    float* __restrict__ C, __half* __restrict__ H, char* smem, int e, int mt,
    int nt) {
    uint32_t sbase = smem_u32(smem);
    int tid = threadIdx.x, wid = tid >> 5, lane = tid & 31;

    int lrow = tid >> 3, lc16 = tid & 7;  // lrow 0..31, lc16 0..7
    const char* gA = (const char*)(A + ((size_t)e * 1024 + mt * 128 + lrow) * K +
                                   lc16 * 8);
    const char* gB = (const char*)(B + ((size_t)e * 2048 + nt * 128 + lrow) * K +
                                   lc16 * 8);
    uint32_t soL = (uint32_t)(lrow * 128 + lc16 * 16);
    soL ^= (soL >> 3) & 0x70;

    float acc[2][8][4];
#pragma unroll
    for (int a = 0; a < 2; a++)
#pragma unroll
        for (int b = 0; b < 8; b++)
#pragma unroll
            for (int c = 0; c < 4; c++) acc[a][b][c] = 0.0f;

    int wm = wid & 3, wn = wid >> 2;  // 4m x 2n

#define LOAD_STAGE(SB, KC)                                                    \
    do {                                                                      \
        const char* a0 = gA + (size_t)(KC)*128;                               \
        const char* b0 = gB + (size_t)(KC)*128;                               \
        _Pragma("unroll") for (int j = 0; j < 4; j++)                         \
            cp16((SB) + soL + j * 4096, a0 + (size_t)j * 32 * (K * 2));       \
        _Pragma("unroll") for (int j = 0; j < 4; j++)                         \
            cp16((SB) + OFF_B + soL + j * 4096, b0 + (size_t)j * 32 * (K * 2));\
    } while (0)

    uint32_t sb[3] = {sbase, sbase + STAGE_BYTES, sbase + 2 * STAGE_BYTES};
    constexpr int kiters = K >> 6;
    LOAD_STAGE(sb[0], 0);
    cp_commit();
    LOAD_STAGE(sb[1], 1);
    cp_commit();

    // swizzled ldsm offsets; sw(base + kd) = sw(base) ^ kd for kd in bits 5-6
    uint32_t aOff[2], bOff[4];
    {
        uint32_t aBase =
            (uint32_t)((wm * 32 + (lane & 15)) * 128 + ((lane >> 4) & 1) * 16);
        uint32_t bBase =
            (uint32_t)((wn * 64 + (lane & 7) + ((lane >> 4) & 1) * 8) * 128 +
                       ((lane >> 3) & 1) * 16);
#pragma unroll
        for (int mf = 0; mf < 2; mf++) {
            uint32_t o = aBase + mf * 2048;
            aOff[mf] = o ^ ((o >> 3) & 0x70);
        }
#pragma unroll
        for (int np = 0; np < 4; np++) {
            uint32_t o = bBase + np * 2048;
            bOff[np] = (o ^ ((o >> 3) & 0x70)) + OFF_B;
        }
    }

#pragma unroll 1
    for (int kc = 0; kc < kiters; kc++) {
        uint32_t s = sb[kc % 3];
        cp_wait<1>();
        __syncthreads();

        uint32_t af[2][2][4], bf[2][4][4];
#pragma unroll
        for (int mf = 0; mf < 2; mf++) ldsm4(af[0][mf], s + aOff[mf]);
#pragma unroll
        for (int np = 0; np < 4; np++) ldsm4(bf[0][np], s + bOff[np]);

#pragma unroll
        for (int k16 = 0; k16 < 4; k16++) {
            int cur = k16 & 1, nxt = cur ^ 1;
            if (k16 < 3) {
                uint32_t kd = (uint32_t)(k16 + 1) * 32;
#pragma unroll
                for (int mf = 0; mf < 2; mf++)
                    ldsm4(af[nxt][mf], s + (aOff[mf] ^ kd));
#pragma unroll
                for (int np = 0; np < 4; np++)
                    ldsm4(bf[nxt][np], s + (bOff[np] ^ kd));
            }
#pragma unroll
            for (int mf = 0; mf < 2; mf++)
#pragma unroll
                for (int np = 0; np < 4; np++) {
                    mma16816(acc[mf][2 * np], af[cur][mf], bf[cur][np][0],
                             bf[cur][np][1]);
                    mma16816(acc[mf][2 * np + 1], af[cur][mf], bf[cur][np][2],
                             bf[cur][np][3]);
                }
        }
        if (kc + 2 < kiters) LOAD_STAGE(sb[(kc + 2) % 3], kc + 2);
        cp_commit();
    }

    // ---- epilogue ----
    int row0 = wm * 32 + (lane >> 2);
    if (FUSE_SILU) {
        size_t grow0 = (size_t)e * 1024 + mt * 128 + row0;
        int hcol = nt * 64 + wn * 32 + (lane & 3);
#pragma unroll
        for (int mf = 0; mf < 2; mf++)
#pragma unroll
            for (int nf = 0; nf < 8; nf++) {
                size_t r = grow0 + mf * 16;
                int hc = hcol + nf * 4;
                float u0 = acc[mf][nf][0], g0 = acc[mf][nf][1];
                float u1 = acc[mf][nf][2], g1 = acc[mf][nf][3];
                float h0 = u0 * g0 * (1.0f / (1.0f + __expf(-g0)));
                float h1 = u1 * g1 * (1.0f / (1.0f + __expf(-g1)));
                H[r * H_DIM + hc] = __float2half(h0);
                H[(r + 8) * H_DIM + hc] = __float2half(h1);
            }
    } else {
        float* pC = C + ((size_t)e * 1024 + mt * 128) * 2048 + nt * 128;
        int col0 = wn * 64 + (lane & 3) * 2;
#pragma unroll
        for (int mf = 0; mf < 2; mf++)
#pragma unroll
            for (int nf = 0; nf < 8; nf++) {
                int r = row0 + mf * 16, c = col0 + nf * 8;
                float2 v0 = {acc[mf][nf][0], acc[mf][nf][1]};
                float2 v1 = {acc[mf][nf][2], acc[mf][nf][3]};
                *reinterpret_cast<float2*>(pC + (size_t)r * 2048 + c) = v0;
                *reinterpret_cast<float2*>(pC + (size_t)(r + 8) * 2048 + c) = v1;
            }
    }
#undef LOAD_STAGE
}

// ------------------------- fused GEMM1+GEMM2 kernel ------------------------
// bids [0, 2048): gemm1 tile; signals counter (e,mt) on completion.
// bids [2048, 4096): gemm2 tile; spins until counter (e,mt) == 16.
// Deadlock-free: CTAs dispatch in bid order, so every producer a consumer
// needs has started before that consumer starts; producers wait on nothing.
__global__ void __launch_bounds__(256, 2) fused_gemm_kernel(
    float* __restrict__ out) {
    extern __shared__ char smem[];
    int bid = blockIdx.x;
    bool is_g2 = bid >= 2048;
    int b = is_g2 ? (bid - 2048) : bid;
    int e = b >> 7, rr = b & 127, mt = rr >> 4, nt = rr & 15;
    int tid = threadIdx.x;

    if (!is_g2) {
        gemm_body<D_DIM, true>(g_xh, g_w1h, nullptr, g_hh, smem, e, mt, nt);
        __threadfence();   // each thread: H stores visible device-wide
        __syncthreads();   // all threads fenced
        if (tid == 0) atomicAdd(&g_cnt[e * 8 + mt], 1u);
    } else {
        if (tid == 0) {
            const unsigned* cp = &g_cnt[e * 8 + mt];
            unsigned v;
            do {
                asm volatile("ld.acquire.gpu.u32 %0, [%1];"
                             : "=r"(v) : "l"(cp) : "memory");
                if (v < 16u) __nanosleep(256);
            } while (v < 16u);
        }
        __syncthreads();   // acquire broadcast to CTA
        gemm_body<H_DIM, false>(g_hh, g_w2th, out, nullptr, smem, e, mt, nt);
    }
}

// ------------------------- launch ------------------------------------------
extern "C" void kernel_launch(void* const* d_in, const int* in_sizes, int n_in,
                              void* d_out, int out_size) {
    (void)in_sizes; (void)n_in; (void)out_size;
    const float* x = (const float*)d_in[0];
    const float* w1 = (const float*)d_in[1];
    const float* w2 = (const float*)d_in[2];
    float* out = (float*)d_out;

    cudaFuncSetAttribute(fused_gemm_kernel,
                         cudaFuncAttributeMaxDynamicSharedMemorySize, GEMM_SMEM);

    __half *xh, *w1h, *w2th;
    unsigned* cnt;
    cudaGetSymbolAddress((void**)&xh, g_xh);
    cudaGetSymbolAddress((void**)&w1h, g_w1h);
    cudaGetSymbolAddress((void**)&w2th, g_w2th);
    cudaGetSymbolAddress((void**)&cnt, g_cnt);

    // reset dependency counters (graph-capturable async memset)
    cudaMemsetAsync(cnt, 0, N_EXP * 8 * sizeof(unsigned));

    // pre-pass: x -> fp16; w1 -> interleaved fp16; w2 -> transposed fp16
    cvt_kernel<<<32768, 256>>>(x, xh);
    interleave_cvt_kernel<<<65536, 256>>>(w1, w1h);
    transpose_cvt_kernel<<<dim3(64, 32, 16), dim3(32, 8)>>>(w2, w2th);

    // fused GEMM1 (+silu) then GEMM2 with fine-grained cross-tile dependency
    fused_gemm_kernel<<<4096, 256, GEMM_SMEM>>>(out);
}